// round 7
// baseline (speedup 1.0000x reference)
#include <cuda_runtime.h>

// NoQmix: q_tot[b] = sum_j agent_qs[b, j]
//
// Exact identity (verified empirically in R4, rel_err 1.7e-7):
// softmax(e, axis=1) sums to 1 per (b,j) column unconditionally, so
// q_tot[b] = sum_j qs[b,j]. Only agent_qs (input 1, [4096, 64] fp32)
// matters: 1.05 MB read + 16 KB write.
//
// R6: thread-per-row with the R5 bug fixed — a row is 64 floats = SIXTEEN
// float4s (R5 only summed the first four -> rel_err 0.863 = sqrt(48/64),
// exactly the variance of the dropped 48 terms). 16 independent LDG.128
// per thread (MLP=16), no shuffle reduction tail.

static constexpr int B_ROWS = 4096;
static constexpr int N_AGENTS = 64;              // 64 floats per row
static constexpr int VECS = N_AGENTS / 4;        // 16 float4 per row

__global__ void noqmix_rowsum_kernel(const float* __restrict__ qs,
                                     float* __restrict__ out) {
    const int row = blockIdx.x * blockDim.x + threadIdx.x;  // grid is exact

    const float4* p = reinterpret_cast<const float4*>(qs) + (size_t)row * VECS;

    // 16 independent loads; compiler front-batches them (MLP=16).
    float4 v[VECS];
#pragma unroll
    for (int i = 0; i < VECS; i++) v[i] = p[i];

    // Pairwise tree reduction over all 64 elements.
    float part[VECS];
#pragma unroll
    for (int i = 0; i < VECS; i++)
        part[i] = (v[i].x + v[i].y) + (v[i].z + v[i].w);

#pragma unroll
    for (int stride = VECS / 2; stride > 0; stride >>= 1)
#pragma unroll
        for (int i = 0; i < stride; i++)
            part[i] += part[i + stride];

    out[row] = part[0];
}

extern "C" void kernel_launch(void* const* d_in, const int* in_sizes, int n_in,
                              void* d_out, int out_size) {
    // Input order: features(0), agent_qs(1), adj(2), states(3), W(4), a(5).
    const float* agent_qs = (const float*)d_in[1];
    float* out = (float*)d_out;

    // 4096 rows, one thread each: 64 blocks x 64 threads (exact, no guard).
    const int threads = 64;
    const int blocks = B_ROWS / threads;   // 64
    noqmix_rowsum_kernel<<<blocks, threads>>>(agent_qs, out);
}

// round 8
// speedup vs baseline: 1.1852x; 1.1852x over previous
#include <cuda_runtime.h>

// NoQmix: q_tot[b] = sum_j agent_qs[b, j]
//
// Exact identity (verified in R4/R6, rel_err 1.7e-7): softmax(e, axis=1)
// sums to 1 per (b,j) column unconditionally, so q_tot[b] = sum_j qs[b,j].
// Only agent_qs (input 1, [4096, 64] fp32) matters: 1.05 MB read + 16 KB write.
//
// R7 layout: R4's coalesced 16-lanes-per-row pattern, but each warp handles
// TWO row-pairs (4 rows): every lane issues 2 independent coalesced LDG.128
// (MLP=2), two independent 4-shuffle reduction chains overlap, 2 stores.
// 1024 warps (128 blocks x 256 threads) keeps the SMs covered for the ramp
// while doubling in-flight loads per warp vs R4.
// R6 lesson: thread-per-row (128 warps, uncoalesced) regressed — warp count
// and coalescing dominate MLP for this latency-bound 1 MB transfer.

static constexpr int B_ROWS = 4096;
static constexpr int N_AGENTS = 64;   // 16 float4 per row

__global__ void noqmix_rowsum_kernel(const float* __restrict__ qs,
                                     float* __restrict__ out) {
    const int gwarp = (blockIdx.x * blockDim.x + threadIdx.x) >> 5;
    const int lane  = threadIdx.x & 31;
    const int sub   = lane >> 4;      // which row of the pair
    const int slane = lane & 15;      // lane within 16-lane row group

    // Warp covers rows [gwarp*4, gwarp*4+4): two R4-style row pairs.
    const int row0 = gwarp * 4 + sub;        // pair 0
    const int row1 = row0 + 2;               // pair 1

    const float4* base = reinterpret_cast<const float4*>(qs);
    // Both loads are fully coalesced: 16 consecutive float4 per row group.
    float4 va = base[(size_t)row0 * (N_AGENTS / 4) + slane];
    float4 vb = base[(size_t)row1 * (N_AGENTS / 4) + slane];

    float sa = (va.x + va.y) + (va.z + va.w);
    float sb = (vb.x + vb.y) + (vb.z + vb.w);

    // Two independent butterfly chains (xor offsets stay inside 16-lane group);
    // the scheduler interleaves them, hiding most of the SHFL latency.
#pragma unroll
    for (int off = 8; off > 0; off >>= 1) {
        sa += __shfl_xor_sync(0xffffffffu, sa, off);
        sb += __shfl_xor_sync(0xffffffffu, sb, off);
    }

    if (slane == 0) {
        out[row0] = sa;
        out[row1] = sb;
    }
}

extern "C" void kernel_launch(void* const* d_in, const int* in_sizes, int n_in,
                              void* d_out, int out_size) {
    // Input order: features(0), agent_qs(1), adj(2), states(3), W(4), a(5).
    const float* agent_qs = (const float*)d_in[1];
    float* out = (float*)d_out;

    // 4096 rows, 4 rows/warp, 8 warps/block -> 32 rows/block -> 128 blocks.
    const int threads = 256;
    const int rows_per_block = (threads / 32) * 4;          // 32
    const int blocks = B_ROWS / rows_per_block;              // 128 (exact)
    noqmix_rowsum_kernel<<<blocks, threads>>>(agent_qs, out);
}